// round 13
// baseline (speedup 1.0000x reference)
#include <cuda_runtime.h>
#include <cuda_bf16.h>
#include <cuda_fp16.h>
#include <math.h>
#include <stdint.h>

// Problem constants
#define LN 12
#define BB 4
#define NN 512
#define SS 512
#define VV 32000
#define HH 768
#define NH 8
#define DH 96
#define MROWS (BB*NN)          // 2048
#define KVLEN (SS+NN)          // 1024
#define LBUF ((long)BB*KVLEN*HH)   // per-layer k/v buffer elems

// ---------------- scratch (device globals; no allocation allowed) ----------
__device__ float g_hidden[MROWS*HH];
__device__ float g_attn[MROWS*HH];
__device__ float g_ffn[MROWS*HH];
__device__ float g_cos[NN*DH];
__device__ float g_sin[NN*DH];
__device__ __half g_qkvh[MROWS*3*HH];
// fp16 attention operands (q pre-scaled by DH^-0.5); k/v per-layer
__device__ __half g_qh[MROWS*HH];
__device__ __half g_kcath[LN*BB*KVLEN*HH];
__device__ __half g_vcath[LN*BB*KVLEN*HH];
// K-major fp16 weights [l][N][K]
__device__ __half g_qkvTh[LN*3*HH*HH];
__device__ __half g_skvTh[LN*HH*HH];
__device__ __half g_outTh[LN*HH*HH];
__device__ __half g_f1Th[LN*HH*HH];
__device__ __half g_f2Th[LN*HH*HH];
__device__ __half g_embedh[(long)VV*HH];

// =================== helpers ================================================
__device__ __forceinline__ uint32_t smem_u32(const void* p) {
    uint32_t a;
    asm("{ .reg .u64 t; cvta.to.shared.u64 t, %1; cvt.u32.u64 %0, t; }"
        : "=r"(a) : "l"(p));
    return a;
}
__device__ __forceinline__ void sts128(uint32_t a, uint4 v) {
    asm volatile("st.shared.v4.b32 [%0], {%1,%2,%3,%4};"
        :: "r"(a), "r"(v.x), "r"(v.y), "r"(v.z), "r"(v.w) : "memory");
}
__device__ __forceinline__ void ldsm4(uint32_t (&r)[4], uint32_t addr) {
    asm volatile("ldmatrix.sync.aligned.m8n8.x4.shared.b16 {%0,%1,%2,%3}, [%4];"
        : "=r"(r[0]), "=r"(r[1]), "=r"(r[2]), "=r"(r[3]) : "r"(addr));
}
__device__ __forceinline__ void ldsm4t(uint32_t (&r)[4], uint32_t addr) {
    asm volatile("ldmatrix.sync.aligned.m8n8.x4.trans.shared.b16 {%0,%1,%2,%3}, [%4];"
        : "=r"(r[0]), "=r"(r[1]), "=r"(r[2]), "=r"(r[3]) : "r"(addr));
}
__device__ __forceinline__ void mma16816(float (&d)[4], const uint32_t (&a)[4],
                                         uint32_t b0, uint32_t b1) {
    asm volatile("mma.sync.aligned.m16n8k16.row.col.f32.f16.f16.f32 "
        "{%0,%1,%2,%3}, {%4,%5,%6,%7}, {%8,%9}, {%0,%1,%2,%3};"
        : "+f"(d[0]), "+f"(d[1]), "+f"(d[2]), "+f"(d[3])
        : "r"(a[0]), "r"(a[1]), "r"(a[2]), "r"(a[3]), "r"(b0), "r"(b1));
}
__device__ __forceinline__ uint32_t pkh2(float x, float y) {
    __half2 t = __floats2half2_rn(x, y);
    return *reinterpret_cast<uint32_t*>(&t);
}
__device__ __forceinline__ float hifh(float x) {
    return __half2float(__float2half_rn(x));
}
__device__ __forceinline__ void cvt8_hl(float4 a, float4 b, uint4& hi, uint4& lo) {
    hi.x = pkh2(a.x, a.y); hi.y = pkh2(a.z, a.w);
    hi.z = pkh2(b.x, b.y); hi.w = pkh2(b.z, b.w);
    lo.x = pkh2(a.x - hifh(a.x), a.y - hifh(a.y));
    lo.y = pkh2(a.z - hifh(a.z), a.w - hifh(a.w));
    lo.z = pkh2(b.x - hifh(b.x), b.y - hifh(b.y));
    lo.w = pkh2(b.z - hifh(b.z), b.w - hifh(b.w));
}
__device__ __forceinline__ uint4 cvt8_p(float4 a, float4 b) {
    uint4 h;
    h.x = pkh2(a.x, a.y); h.y = pkh2(a.z, a.w);
    h.z = pkh2(b.x, b.y); h.w = pkh2(b.z, b.w);
    return h;
}
__device__ __forceinline__ float4 scl4(float4 v, float s) {
    return make_float4(v.x*s, v.y*s, v.z*s, v.w*s);
}

// =================== mma.sync fp16 GEMM (templated) =========================
// C[M,N] = rms?(A)[M,P] @ BT[N,P]^T (+bias)(+res)(gelu).
// TP: A hi/lo compensated 2-pass. OH: fp16 output. RMS: per-row
// rsqrt(mean(A^2)+eps) applied to A during staging (norm weight folded in BT).
// gridDim.z batching: z&1 selects A/A2,C/C2; z>>1 adds lsA/lsC layer strides.
#define KS 32

template<int BM, int NT, bool TP, bool OH, bool RMS>
__global__ void __launch_bounds__(NT, 1) mgemm_k(
    const float* __restrict__ A, const float* __restrict__ A2,
    const __half* __restrict__ BT,
    const float* __restrict__ bias, const float* res, void* Cv, void* Cv2,
    int M, int P, int N, int act, int rowseg, long long segstride,
    long lsA, long lsC)
{
    constexpr int ALOx = BM * 64;
    constexpr int BHIx = TP ? 2 * ALOx : ALOx;
    constexpr int STGx = BHIx + 8192;
    constexpr int NA = (BM * 4) / NT;
    constexpr int NB = 512 / NT;

    extern __shared__ char smemb[];
    const uint32_t sb = smem_u32(smemb);
    float* invp = (float*)(smemb + 2*STGx);
    const int tid = threadIdx.x, lane = tid & 31, wid = tid >> 5;
    const int wr = wid >> 2, wc = wid & 3;
    const int row0 = blockIdx.y * BM, col0 = blockIdx.x * 128;
    const int zl = blockIdx.z >> 1;
    const float* Ab = ((blockIdx.z & 1) ? A2 : A) + (long)zl * lsA;
    void* Cb;
    if (OH) Cb = (void*)((__half*)((blockIdx.z & 1) ? Cv2 : Cv) + (long)zl * lsC);
    else    Cb = (void*)((float*)((blockIdx.z & 1) ? Cv2 : Cv) + (long)zl * lsC);
    const __half* BTl = BT + (long)zl * 0;  // BT not layer-strided here

    // RMS pre-pass: 4 threads per row, quad-shuffle reduce
    if (RMS) {
        int r = tid >> 2, seg = tid & 3;
        const float* rp = Ab + (long)(row0 + r) * P + seg * (P >> 2);
        float ss = 0.f;
        for (int i = 0; i < (P >> 2); i += 4) {
            float4 v = *(const float4*)(rp + i);
            ss += v.x*v.x + v.y*v.y + v.z*v.z + v.w*v.w;
        }
        ss += __shfl_xor_sync(0xffffffffu, ss, 1);
        ss += __shfl_xor_sync(0xffffffffu, ss, 2);
        if (seg == 0) invp[r] = rsqrtf(ss / (float)P + 1e-6f);
        __syncthreads();
    }

    const int g = lane >> 3, ri = lane & 7;
    uint32_t aoff[2]; uint32_t asw[2];
    #pragma unroll
    for (int f = 0; f < 2; f++) {
        int m = wr*32 + f*16 + (g & 1)*8 + ri;
        aoff[f] = m * 64; asw[f] = (m >> 1) & 3;
    }
    const uint32_t qa = g >> 1;
    uint32_t boff[2]; uint32_t bsw[2];
    #pragma unroll
    for (int p = 0; p < 2; p++) {
        int n = wc*32 + p*16 + (g >> 1)*8 + ri;
        boff[p] = n * 64; bsw[p] = (n >> 1) & 3;
    }
    const uint32_t qb = g & 1;

    float acc[2][4][4];
    #pragma unroll
    for (int f = 0; f < 2; f++)
        #pragma unroll
        for (int j = 0; j < 4; j++)
            #pragma unroll
            for (int e = 0; e < 4; e++) acc[f][j][e] = 0.f;

    int arow[NA], aq[NA];
    #pragma unroll
    for (int i = 0; i < NA; i++) { int t = tid + i*NT; arow[i] = t >> 2; aq[i] = t & 3; }
    int brow[NB], bq[NB];
    #pragma unroll
    for (int j = 0; j < NB; j++) {
        int t = tid + (NA + j)*NT; brow[j] = (t >> 2) - BM; bq[j] = t & 3;
    }

    float4 sa0[NA], sa1[NA]; uint4 sbv[NB];
    const int NS = P / KS;

    auto loadg = [&](int k0) {
        #pragma unroll
        for (int i = 0; i < NA; i++) {
            const float* p = Ab + (long)(row0 + arow[i]) * P + k0 + aq[i]*8;
            sa0[i] = *(const float4*)p; sa1[i] = *(const float4*)(p + 4);
        }
        #pragma unroll
        for (int j = 0; j < NB; j++)
            sbv[j] = *(const uint4*)(BTl + (long)(col0 + brow[j]) * P + k0 + bq[j]*8);
    };
    auto stores = [&](uint32_t base) {
        #pragma unroll
        for (int i = 0; i < NA; i++) {
            uint32_t off = arow[i]*64 + (((uint32_t)aq[i] ^ ((arow[i]>>1)&3)) << 4);
            float4 a0 = sa0[i], a1 = sa1[i];
            if (RMS) { float iv = invp[arow[i]]; a0 = scl4(a0, iv); a1 = scl4(a1, iv); }
            if (TP) {
                uint4 hi, lo; cvt8_hl(a0, a1, hi, lo);
                sts128(base + off, hi); sts128(base + ALOx + off, lo);
            } else {
                sts128(base + off, cvt8_p(a0, a1));
            }
        }
        #pragma unroll
        for (int j = 0; j < NB; j++) {
            uint32_t off = brow[j]*64 + (((uint32_t)bq[j] ^ ((brow[j]>>1)&3)) << 4);
            sts128(base + BHIx + off, sbv[j]);
        }
    };

    loadg(0);
    stores(sb);
    __syncthreads();

    for (int s = 0; s < NS; s++) {
        const uint32_t cb = sb + (s & 1) * STGx;
        if (s + 1 < NS) loadg((s + 1) * KS);

        #pragma unroll
        for (int kst = 0; kst < 2; kst++) {
            uint32_t ah[2][4], bh[2][4];
            #pragma unroll
            for (int f = 0; f < 2; f++) {
                uint32_t off = aoff[f] + ((((uint32_t)(kst*2) + qa) ^ asw[f]) << 4);
                ldsm4(ah[f], cb + off);
            }
            #pragma unroll
            for (int p = 0; p < 2; p++) {
                uint32_t off = boff[p] + ((((uint32_t)(kst*2) + qb) ^ bsw[p]) << 4);
                ldsm4(bh[p], cb + BHIx + off);
            }
            #pragma unroll
            for (int f = 0; f < 2; f++)
                #pragma unroll
                for (int j = 0; j < 4; j++)
                    mma16816(acc[f][j], ah[f], bh[j>>1][(j&1)*2], bh[j>>1][(j&1)*2+1]);
            if (TP) {
                uint32_t al[2][4];
                #pragma unroll
                for (int f = 0; f < 2; f++) {
                    uint32_t off = aoff[f] + ((((uint32_t)(kst*2) + qa) ^ asw[f]) << 4);
                    ldsm4(al[f], cb + ALOx + off);
                }
                #pragma unroll
                for (int f = 0; f < 2; f++)
                    #pragma unroll
                    for (int j = 0; j < 4; j++)
                        mma16816(acc[f][j], al[f], bh[j>>1][(j&1)*2], bh[j>>1][(j&1)*2+1]);
            }
        }

        if (s + 1 < NS) stores(sb + ((s + 1) & 1) * STGx);
        __syncthreads();
    }

    // epilogue
    #pragma unroll
    for (int f = 0; f < 2; f++) {
        #pragma unroll
        for (int j = 0; j < 4; j++) {
            int r = row0 + wr*32 + f*16 + (lane >> 2);
            int c = col0 + wc*32 + j*8 + (lane & 3)*2;
            #pragma unroll
            for (int half = 0; half < 2; half++) {
                int rr = r + half*8;
                float x0 = acc[f][j][half*2], x1 = acc[f][j][half*2+1];
                if (bias) { x0 += bias[c]; x1 += bias[c+1]; }
                if (res)  {
                    const float* rp = res + (long)rr*N + c;
                    x0 += rp[0]; x1 += rp[1];
                }
                if (act == 1) {
                    x0 = 0.5f*x0*(1.f + erff(x0*0.70710678118654752f));
                    x1 = 0.5f*x1*(1.f + erff(x1*0.70710678118654752f));
                }
                long ob = (long)(rr / rowseg) * segstride + (long)(rr % rowseg) * N + c;
                if (OH) {
                    __half2 hv = __floats2half2_rn(x0, x1);
                    *(__half2*)((__half*)Cb + ob) = hv;
                } else {
                    *(float2*)((float*)Cb + ob) = make_float2(x0, x1);
                }
            }
        }
    }
}

// =================== tensor-core flash attention (fp16 in) ==================
#define AT_QS 0
#define AT_KS 12288
#define AT_VS 24576
#define AT_SMEM (24576 + 64*208)

__global__ __launch_bounds__(128, 1) void attn3_k(
    const __half* __restrict__ q, const __half* __restrict__ kcat,
    const __half* __restrict__ vcat, float* __restrict__ out)
{
    extern __shared__ char smemb[];
    const uint32_t sb = smem_u32(smemb);
    const int qt = blockIdx.x, h = blockIdx.y, b = blockIdx.z;
    const int tid = threadIdx.x, lane = tid & 31, wid = tid >> 5;
    const int g = lane >> 3, ri = lane & 7;

    for (int t = tid; t < 768; t += 128) {
        int row = t / 12, c = t % 12, slab = c >> 2, cc = c & 3;
        uint4 hv = *(const uint4*)(q + (long)(b*NN + qt*64 + row)*HH + h*DH + c*8);
        uint32_t off = slab*4096 + row*64 + (((uint32_t)cc ^ ((row>>1)&3)) << 4);
        sts128(sb + AT_QS + off, hv);
    }
    __syncthreads();

    uint32_t qf[6][4];
    {
        int mrow = wid*16 + (g & 1)*8 + ri;
        uint32_t qa = g >> 1, asw = (mrow >> 1) & 3;
        #pragma unroll
        for (int k16 = 0; k16 < 6; k16++) {
            int slab = k16 >> 1, kst = k16 & 1;
            uint32_t off = slab*4096 + mrow*64
                         + ((((uint32_t)(kst*2) + qa) ^ asw) << 4);
            ldsm4(qf[k16], sb + AT_QS + off);
        }
    }

    float O[12][4];
    #pragma unroll
    for (int o = 0; o < 12; o++)
        #pragma unroll
        for (int e = 0; e < 4; e++) O[o][e] = 0.f;
    float m0 = -1e30f, m1 = -1e30f, l0 = 0.f, l1 = 0.f;

    const int nrow = (g >> 1)*8 + ri;
    const uint32_t qb = g & 1;
    const int vr = (lane & 7) + ((lane >> 3) & 1)*8;
    const int vc16 = (lane >> 4)*16;
    const int ntiles = SS/64 + qt + 1;

    for (int jt = 0; jt < ntiles; jt++) {
        __syncthreads();
        for (int t = tid; t < 768; t += 128) {
            int row = t / 12, c = t % 12;
            long jr = ((long)b*KVLEN + jt*64 + row)*HH + h*DH;
            int slab = c >> 2, cc = c & 3;
            uint4 hk = *(const uint4*)(kcat + jr + c*8);
            uint32_t koff = slab*4096 + row*64 + (((uint32_t)cc ^ ((row>>1)&3)) << 4);
            sts128(sb + AT_KS + koff, hk);
            uint4 hv = *(const uint4*)(vcat + jr + c*8);
            sts128(sb + AT_VS + row*208 + c*16, hv);
        }
        __syncthreads();

        float S[8][4];
        #pragma unroll
        for (int t8 = 0; t8 < 8; t8++)
            #pragma unroll
            for (int e = 0; e < 4; e++) S[t8][e] = 0.f;

        #pragma unroll
        for (int k16 = 0; k16 < 6; k16++) {
            int slab = k16 >> 1, kst = k16 & 1;
            #pragma unroll
            for (int p = 0; p < 4; p++) {
                int brow = p*16 + nrow;
                uint32_t off = slab*4096 + brow*64
                             + ((((uint32_t)(kst*2) + qb) ^ ((brow>>1)&3)) << 4);
                uint32_t bh[4];
                ldsm4(bh, sb + AT_KS + off);
                mma16816(S[2*p],     qf[k16], bh[0], bh[1]);
                mma16816(S[2*p + 1], qf[k16], bh[2], bh[3]);
            }
        }

        if (jt == ntiles - 1) {
            int r0 = wid*16 + (lane >> 2);
            #pragma unroll
            for (int t8 = 0; t8 < 8; t8++)
                #pragma unroll
                for (int e = 0; e < 2; e++) {
                    int col = t8*8 + 2*(lane & 3) + e;
                    if (col > r0)     S[t8][e]     = -1e30f;
                    if (col > r0 + 8) S[t8][2 + e] = -1e30f;
                }
        }

        float mx0 = -1e30f, mx1 = -1e30f;
        #pragma unroll
        for (int t8 = 0; t8 < 8; t8++) {
            mx0 = fmaxf(mx0, fmaxf(S[t8][0], S[t8][1]));
            mx1 = fmaxf(mx1, fmaxf(S[t8][2], S[t8][3]));
        }
        mx0 = fmaxf(mx0, __shfl_xor_sync(0xffffffffu, mx0, 1));
        mx0 = fmaxf(mx0, __shfl_xor_sync(0xffffffffu, mx0, 2));
        mx1 = fmaxf(mx1, __shfl_xor_sync(0xffffffffu, mx1, 1));
        mx1 = fmaxf(mx1, __shfl_xor_sync(0xffffffffu, mx1, 2));
        float mn0 = fmaxf(m0, mx0), mn1 = fmaxf(m1, mx1);
        float f0 = __expf(m0 - mn0), f1 = __expf(m1 - mn1);
        float s0 = 0.f, s1 = 0.f;
        #pragma unroll
        for (int t8 = 0; t8 < 8; t8++) {
            S[t8][0] = __expf(S[t8][0] - mn0); s0 += S[t8][0];
            S[t8][1] = __expf(S[t8][1] - mn0); s0 += S[t8][1];
            S[t8][2] = __expf(S[t8][2] - mn1); s1 += S[t8][2];
            S[t8][3] = __expf(S[t8][3] - mn1); s1 += S[t8][3];
        }
        s0 += __shfl_xor_sync(0xffffffffu, s0, 1);
        s0 += __shfl_xor_sync(0xffffffffu, s0, 2);
        s1 += __shfl_xor_sync(0xffffffffu, s1, 1);
        s1 += __shfl_xor_sync(0xffffffffu, s1, 2);
        l0 = l0*f0 + s0; l1 = l1*f1 + s1;
        m0 = mn0; m1 = mn1;
        #pragma unroll
        for (int o = 0; o < 12; o++) {
            O[o][0] *= f0; O[o][1] *= f0;
            O[o][2] *= f1; O[o][3] *= f1;
        }

        uint32_t pa[4][4];
        #pragma unroll
        for (int j16 = 0; j16 < 4; j16++) {
            pa[j16][0] = pkh2(S[2*j16][0],     S[2*j16][1]);
            pa[j16][1] = pkh2(S[2*j16][2],     S[2*j16][3]);
            pa[j16][2] = pkh2(S[2*j16 + 1][0], S[2*j16 + 1][1]);
            pa[j16][3] = pkh2(S[2*j16 + 1][2], S[2*j16 + 1][3]);
        }
        #pragma unroll
        for (int j16 = 0; j16 < 4; j16++) {
            #pragma unroll
            for (int v16 = 0; v16 < 6; v16++) {
                uint32_t bv[4];
                ldsm4t(bv, sb + AT_VS + (j16*16 + vr)*208 + v16*32 + vc16);
                mma16816(O[2*v16],     pa[j16], bv[0], bv[1]);
                mma16816(O[2*v16 + 1], pa[j16], bv[2], bv[3]);
            }
        }
    }

    float i0 = 1.f / l0, i1 = 1.f / l1;
    long rbase = (long)(b*NN + qt*64 + wid*16 + (lane >> 2))*HH + h*DH + 2*(lane & 3);
    #pragma unroll
    for (int t8 = 0; t8 < 12; t8++) {
        *(float2*)(out + rbase + t8*8) = make_float2(O[t8][0]*i0, O[t8][1]*i0);
        *(float2*)(out + rbase + 8*HH + t8*8) = make_float2(O[t8][2]*i1, O[t8][3]*i1);
    }
}

// ---------------- weight transpose+fp16 (+ optional rmsnorm weight fold) ----
// WT[l][n][k] = W[l][k][n] * (1 + nw[l][k])  (nw==nullptr -> no fold)
__global__ void transpose_wh_k(const float* __restrict__ W, __half* __restrict__ WT,
                               int C, const float* __restrict__ nw) {
    __shared__ float tile[32][33];
    int bx = blockIdx.x, by = blockIdx.y, z = blockIdx.z;
    int tx = threadIdx.x, ty = threadIdx.y;
    const float* src = W + (long)z * HH * C;
    __half* dst = WT + (long)z * C * HH;
    #pragma unroll
    for (int j = 0; j < 32; j += 8)
        tile[ty + j][tx] = src[(long)(by * 32 + ty + j) * C + bx * 32 + tx];
    __syncthreads();
    float fac = nw ? (1.f + nw[z*HH + by*32 + tx]) : 1.f;
    #pragma unroll
    for (int j = 0; j < 32; j += 8)
        dst[(long)(bx * 32 + ty + j) * HH + by * 32 + tx] =
            __float2half_rn(tile[tx][ty + j] * fac);
}

// ---------------- fp32 -> fp16 elementwise (8 per thread, vectorized) -------
__global__ void cvt_half_k(const float4* __restrict__ E, uint4* __restrict__ O,
                           long n8) {
    long i = (long)blockIdx.x * blockDim.x + threadIdx.x;
    if (i >= n8) return;
    O[i] = cvt8_p(E[2*i], E[2*i + 1]);
}

// ---------------- embedding gather + scale ----------------------------------
__global__ void embed_k(const int* __restrict__ ids, const float* __restrict__ E,
                        float* __restrict__ hid) {
    long idx = (long)blockIdx.x * blockDim.x + threadIdx.x;
    if (idx >= (long)MROWS*HH) return;
    int col = (int)(idx % HH);
    long row = idx / HH;
    hid[idx] = E[(long)ids[row]*HH + col] * 27.712812921102035f; // sqrt(768)
}

// ---------------- RoPE cos/sin table ----------------------------------------
__global__ void rope_tab_k(float* __restrict__ ct, float* __restrict__ st) {
    int idx = blockIdx.x * blockDim.x + threadIdx.x;
    if (idx >= NN*DH) return;
    int n = idx / DH, dd = idx % DH;
    int t = (dd < DH/2) ? dd : dd - DH/2;
    float invf = __powf(10000.f, -((float)(2*t) / (float)DH));
    float fd = (float)n * invf;
    ct[idx] = cosf(fd);
    st[idx] = sinf(fd);
}

// ---------------- RoPE + q/k/v split-scatter (fp16 in/out, q pre-scaled) ----
__global__ void rope_split_k(const __half* __restrict__ qkv, __half* __restrict__ qh,
                             __half* __restrict__ kcat, __half* __restrict__ vcat,
                             const float* __restrict__ ct, const float* __restrict__ st) {
    long idx = (long)blockIdx.x * blockDim.x + threadIdx.x;
    if (idx >= (long)MROWS*HH) return;
    int col = (int)(idx % HH);
    long row = idx / HH;
    int n = (int)(row % NN);
    int b = (int)(row / NN);
    int dd = col % DH;
    const __half* base = qkv + row*(3*HH);
    float qv = __half2float(base[col]);
    float kv = __half2float(base[HH + col]);
    float vv = __half2float(base[2*HH + col]);
    float c = ct[n*DH + dd], s = st[n*DH + dd];
    float qrot = (dd < DH/2) ? -__half2float(base[col + DH/2])
                             :  __half2float(base[col - DH/2]);
    float krot = (dd < DH/2) ? -__half2float(base[HH + col + DH/2])
                             :  __half2float(base[HH + col - DH/2]);
    const float scale = 0.10206207261596575f; // 96^-0.5
    qh[row*HH + col] = __float2half_rn((qv*c + qrot*s) * scale);
    long outk = ((long)b*KVLEN + SS + n)*HH + col;
    kcat[outk] = __float2half_rn(kv*c + krot*s);
    vcat[outk] = __float2half_rn(vv);
}

// ---------------- host launchers ---------------------------------------------
template<int BM, int NT, bool TP, bool OH, bool RMS>
static void mg_t(const float* A, const float* A2, const __half* BT,
                 const float* bias, const float* res, void* C, void* C2,
                 int M, int P, int N, int act, int rowseg, long long segstride,
                 int nz = 1, long lsA = 0, long lsC = 0) {
    constexpr int ALOx = BM * 64;
    constexpr int BHIx = TP ? 2 * ALOx : ALOx;
    constexpr int STGx = BHIx + 8192;
    constexpr int smem = 2*STGx + (RMS ? BM*4 : 0);
    dim3 grid(N / 128, M / BM, nz);
    mgemm_k<BM, NT, TP, OH, RMS><<<grid, NT, smem>>>(A, A2, BT, bias, res, C, C2,
                                                     M, P, N, act, rowseg, segstride,
                                                     lsA, lsC);
}

extern "C" void kernel_launch(void* const* d_in, const int* in_sizes, int n_in,
                              void* d_out, int out_size) {
    const int*   ids    = (const int*)  d_in[0];
    const float* vkey   = (const float*)d_in[1];   // [L,B,S,H]
    const float* vval   = (const float*)d_in[2];
    const float* embedW = (const float*)d_in[3];   // [V,H]
    const float* n1w    = (const float*)d_in[4];
    const float* n2w    = (const float*)d_in[5];
    const float* qkvW   = (const float*)d_in[6];   // [L,H,3H]
    const float* qkvB   = (const float*)d_in[7];
    const float* skvW   = (const float*)d_in[8];
    const float* skvB   = (const float*)d_in[9];
    const float* outW   = (const float*)d_in[10];
    const float* outB   = (const float*)d_in[11];
    const float* f1W    = (const float*)d_in[12];
    const float* f1B    = (const float*)d_in[13];
    const float* f2W    = (const float*)d_in[14];
    const float* f2B    = (const float*)d_in[15];
    float* logits = (float*)d_out;

    float *hid, *attn, *ffn, *ct, *st;
    __half *qkvh, *qh, *kch, *vch;
    __half *qkvTh, *skvTh, *outTh, *f1Th, *f2Th, *embh;
    cudaGetSymbolAddress((void**)&hid,   g_hidden);
    cudaGetSymbolAddress((void**)&attn,  g_attn);
    cudaGetSymbolAddress((void**)&ffn,   g_ffn);
    cudaGetSymbolAddress((void**)&ct,    g_cos);
    cudaGetSymbolAddress((void**)&st,    g_sin);
    cudaGetSymbolAddress((void**)&qkvh,  g_qkvh);
    cudaGetSymbolAddress((void**)&qh,    g_qh);
    cudaGetSymbolAddress((void**)&kch,   g_kcath);
    cudaGetSymbolAddress((void**)&vch,   g_vcath);
    cudaGetSymbolAddress((void**)&qkvTh, g_qkvTh);
    cudaGetSymbolAddress((void**)&skvTh, g_skvTh);
    cudaGetSymbolAddress((void**)&outTh, g_outTh);
    cudaGetSymbolAddress((void**)&f1Th,  g_f1Th);
    cudaGetSymbolAddress((void**)&f2Th,  g_f2Th);
    cudaGetSymbolAddress((void**)&embh,  g_embedh);

    cudaFuncSetAttribute((const void*)mgemm_k<128,512,false,true,true>,
                         cudaFuncAttributeMaxDynamicSharedMemorySize, 33280);
    cudaFuncSetAttribute((const void*)mgemm_k<128,512,false,true,false>,
                         cudaFuncAttributeMaxDynamicSharedMemorySize, 32768);
    cudaFuncSetAttribute((const void*)mgemm_k<128,512,false,false,false>,
                         cudaFuncAttributeMaxDynamicSharedMemorySize, 32768);
    cudaFuncSetAttribute((const void*)mgemm_k<64,256,true,false,false>,
                         cudaFuncAttributeMaxDynamicSharedMemorySize, 32768);
    cudaFuncSetAttribute((const void*)mgemm_k<64,256,true,false,true>,
                         cudaFuncAttributeMaxDynamicSharedMemorySize, 33024);
    cudaFuncSetAttribute(attn3_k, cudaFuncAttributeMaxDynamicSharedMemorySize, AT_SMEM);

    // weight transposes into K-major fp16 (norm weights folded where consumed)
    transpose_wh_k<<<dim3(3*HH/32, HH/32, LN), dim3(32, 8)>>>(qkvW, qkvTh, 3*HH, n1w);
    transpose_wh_k<<<dim3(HH/32, HH/32, LN), dim3(32, 8)>>>(skvW, skvTh, HH, nullptr);
    transpose_wh_k<<<dim3(HH/32, HH/32, LN), dim3(32, 8)>>>(outW, outTh, HH, nullptr);
    transpose_wh_k<<<dim3(HH/32, HH/32, LN), dim3(32, 8)>>>(f1W,  f1Th,  HH, n2w);
    transpose_wh_k<<<dim3(HH/32, HH/32, LN), dim3(32, 8)>>>(f2W,  f2Th,  HH, nullptr);
    {
        long n8 = (long)VV * HH / 8;
        cvt_half_k<<<(int)((n8 + 255) / 256), 256>>>(
            (const float4*)embedW, (uint4*)embh, n8);
    }

    const int elemBlocks = (MROWS*HH + 255) / 256;
    embed_k<<<elemBlocks, 256>>>(ids, embedW, hid);
    rope_tab_k<<<(NN*DH + 255)/256, 256>>>(ct, st);

    const long HW  = (long)HH * HH;
    const long BSH = (long)BB * SS * HH;

    // ALL skv GEMMs hoisted: one batched launch over 12 layers x {key,val}.
    // NOTE: BT is per-layer via... BT not strided in-kernel; launch per-layer
    // would defeat batching — instead the weights ARE layer-strided: pass the
    // full skvTh and encode the layer in lsA/lsC plus a B stride trick:
    // B rows for layer l live at skvTh + l*HW; since BT isn't z-strided in the
    // kernel, launch 12 z-pairs with one launch by exploiting that lsA strides
    // A and lsC strides C — B must also stride. Handled via nz loop below
    // (single launch per layer pair is still 12 launches; instead we bake the
    // layer into z by passing lsB through BT pointer arithmetic — the kernel
    // uses BTl = BT + zl*0, so we must launch with grid.z=2 per layer).
    for (int l = 0; l < LN; l++) {
        mg_t<128,512,false,true,false>(vkey + (long)l*BSH, vval + (long)l*BSH,
                                       skvTh + l*HW, skvB + l*HH, nullptr,
                                       kch + l*LBUF, vch + l*LBUF,
                                       MROWS, HH, HH, 0, SS, (long long)KVLEN*HH, 2);
    }

    for (int l = 0; l < LN; l++) {
        // qkv GEMM with fused RMSNorm (norm1 folded into qkvTh), fp16 out
        mg_t<128,512,false,true,true>(hid, nullptr, qkvTh + (long)l*3*HW,
                                      qkvB + l*3*HH, nullptr, qkvh, nullptr,
                                      MROWS, HH, 3*HH, 0, MROWS, 0);
        rope_split_k<<<elemBlocks, 256>>>(qkvh, qh, kch + l*LBUF, vch + l*LBUF,
                                          ct, st);
        attn3_k<<<dim3(NN/64, NH, BB), 128, AT_SMEM>>>(qh, kch + l*LBUF,
                                                       vch + l*LBUF, attn);
        mg_t<64,256,true,false,false>(attn, nullptr, outTh + l*HW, outB + l*HH,
                                      hid, hid, nullptr,
                                      MROWS, HH, HH, 0, MROWS, 0);
        // ffn1 with fused RMSNorm (norm2 folded into f1Th) + gelu
        mg_t<64,256,true,false,true>(hid, nullptr, f1Th + l*HW, f1B + l*HH,
                                     nullptr, ffn, nullptr,
                                     MROWS, HH, HH, 1, MROWS, 0);
        mg_t<64,256,true,false,false>(ffn, nullptr, f2Th + l*HW, f2B + l*HH,
                                      hid, hid, nullptr,
                                      MROWS, HH, HH, 0, MROWS, 0);
    }

    // tied lm_head: 1-pass fp16
    mg_t<128,512,false,false,false>(hid, nullptr, embh, nullptr, nullptr,
                                    logits, nullptr, MROWS, HH, VV, 0, MROWS, 0);
}

// round 14
// speedup vs baseline: 1.1654x; 1.1654x over previous
#include <cuda_runtime.h>
#include <cuda_bf16.h>
#include <cuda_fp16.h>
#include <math.h>
#include <stdint.h>

// Problem constants
#define LN 12
#define BB 4
#define NN 512
#define SS 512
#define VV 32000
#define HH 768
#define NH 8
#define DH 96
#define MROWS (BB*NN)          // 2048
#define KVLEN (SS+NN)          // 1024
#define LBUF ((long)BB*KVLEN*HH)   // per-layer k/v buffer elems

// ---------------- scratch (device globals; no allocation allowed) ----------
__device__ float g_hidden[MROWS*HH];
__device__ float g_attn[MROWS*HH];
__device__ float g_ffn[MROWS*HH];
__device__ float g_rmsinv[MROWS];
__device__ float g_cos[NN*DH];
__device__ float g_sin[NN*DH];
__device__ __half g_qkvh[MROWS*3*HH];
// fp16 attention operands (q pre-scaled by DH^-0.5); k/v per-layer
__device__ __half g_qh[MROWS*HH];
__device__ __half g_kcath[LN*BB*KVLEN*HH];
__device__ __half g_vcath[LN*BB*KVLEN*HH];
// K-major fp16 weights [l][N][K]
__device__ __half g_qkvTh[LN*3*HH*HH];
__device__ __half g_skvTh[LN*HH*HH];
__device__ __half g_outTh[LN*HH*HH];
__device__ __half g_f1Th[LN*HH*HH];
__device__ __half g_f2Th[LN*HH*HH];
__device__ __half g_embedh[(long)VV*HH];

// =================== helpers ================================================
__device__ __forceinline__ uint32_t smem_u32(const void* p) {
    uint32_t a;
    asm("{ .reg .u64 t; cvta.to.shared.u64 t, %1; cvt.u32.u64 %0, t; }"
        : "=r"(a) : "l"(p));
    return a;
}
__device__ __forceinline__ void sts128(uint32_t a, uint4 v) {
    asm volatile("st.shared.v4.b32 [%0], {%1,%2,%3,%4};"
        :: "r"(a), "r"(v.x), "r"(v.y), "r"(v.z), "r"(v.w) : "memory");
}
__device__ __forceinline__ void ldsm4(uint32_t (&r)[4], uint32_t addr) {
    asm volatile("ldmatrix.sync.aligned.m8n8.x4.shared.b16 {%0,%1,%2,%3}, [%4];"
        : "=r"(r[0]), "=r"(r[1]), "=r"(r[2]), "=r"(r[3]) : "r"(addr));
}
__device__ __forceinline__ void ldsm4t(uint32_t (&r)[4], uint32_t addr) {
    asm volatile("ldmatrix.sync.aligned.m8n8.x4.trans.shared.b16 {%0,%1,%2,%3}, [%4];"
        : "=r"(r[0]), "=r"(r[1]), "=r"(r[2]), "=r"(r[3]) : "r"(addr));
}
__device__ __forceinline__ void mma16816(float (&d)[4], const uint32_t (&a)[4],
                                         uint32_t b0, uint32_t b1) {
    asm volatile("mma.sync.aligned.m16n8k16.row.col.f32.f16.f16.f32 "
        "{%0,%1,%2,%3}, {%4,%5,%6,%7}, {%8,%9}, {%0,%1,%2,%3};"
        : "+f"(d[0]), "+f"(d[1]), "+f"(d[2]), "+f"(d[3])
        : "r"(a[0]), "r"(a[1]), "r"(a[2]), "r"(a[3]), "r"(b0), "r"(b1));
}
__device__ __forceinline__ uint32_t pkh2(float x, float y) {
    __half2 t = __floats2half2_rn(x, y);
    return *reinterpret_cast<uint32_t*>(&t);
}
__device__ __forceinline__ float hifh(float x) {
    return __half2float(__float2half_rn(x));
}
__device__ __forceinline__ void cvt8_hl(float4 a, float4 b, uint4& hi, uint4& lo) {
    hi.x = pkh2(a.x, a.y); hi.y = pkh2(a.z, a.w);
    hi.z = pkh2(b.x, b.y); hi.w = pkh2(b.z, b.w);
    lo.x = pkh2(a.x - hifh(a.x), a.y - hifh(a.y));
    lo.y = pkh2(a.z - hifh(a.z), a.w - hifh(a.w));
    lo.z = pkh2(b.x - hifh(b.x), b.y - hifh(b.y));
    lo.w = pkh2(b.z - hifh(b.z), b.w - hifh(b.w));
}
__device__ __forceinline__ uint4 cvt8_p(float4 a, float4 b) {
    uint4 h;
    h.x = pkh2(a.x, a.y); h.y = pkh2(a.z, a.w);
    h.z = pkh2(b.x, b.y); h.w = pkh2(b.z, b.w);
    return h;
}
__device__ __forceinline__ float4 scl4(float4 v, float s) {
    return make_float4(v.x*s, v.y*s, v.z*s, v.w*s);
}

// =================== mma.sync fp16 GEMM (templated) =========================
// C[M,N] = (invG?*A)[M,P] @ BT[N,P]^T (+bias)(+res)(gelu).
// TP: A hi/lo compensated 2-pass. OH: fp16 output. RMS: scale A row r by
// invG[r] during staging (precomputed rmsnorm; norm weight folded into BT).
// gridDim.z batching: z&1 selects A/A2,C/C2; zl=z>>1 strides A,B,C,bias.
#define KS 32

template<int BM, int NT, bool TP, bool OH, bool RMS>
__global__ void __launch_bounds__(NT, 1) mgemm_k(
    const float* __restrict__ A, const float* __restrict__ A2,
    const __half* __restrict__ BT, const float* __restrict__ invG,
    const float* __restrict__ bias, const float* res, void* Cv, void* Cv2,
    int M, int P, int N, int act, int rowseg, long long segstride,
    long lsA, long lsC, long lsB, long lsBias)
{
    constexpr int ALOx = BM * 64;
    constexpr int BHIx = TP ? 2 * ALOx : ALOx;
    constexpr int STGx = BHIx + 8192;
    constexpr int NA = (BM * 4) / NT;
    constexpr int NB = 512 / NT;

    extern __shared__ char smemb[];
    const uint32_t sb = smem_u32(smemb);
    const int tid = threadIdx.x, lane = tid & 31, wid = tid >> 5;
    const int wr = wid >> 2, wc = wid & 3;
    const int row0 = blockIdx.y * BM, col0 = blockIdx.x * 128;
    const int zl = blockIdx.z >> 1;
    const float* Ab = ((blockIdx.z & 1) ? A2 : A) + (long)zl * lsA;
    void* Cb;
    if (OH) Cb = (void*)((__half*)((blockIdx.z & 1) ? Cv2 : Cv) + (long)zl * lsC);
    else    Cb = (void*)((float*)((blockIdx.z & 1) ? Cv2 : Cv) + (long)zl * lsC);
    const __half* BTl = BT + (long)zl * lsB;
    const float* biasl = bias ? (bias + (long)zl * lsBias) : nullptr;

    const int g = lane >> 3, ri = lane & 7;
    uint32_t aoff[2]; uint32_t asw[2];
    #pragma unroll
    for (int f = 0; f < 2; f++) {
        int m = wr*32 + f*16 + (g & 1)*8 + ri;
        aoff[f] = m * 64; asw[f] = (m >> 1) & 3;
    }
    const uint32_t qa = g >> 1;
    uint32_t boff[2]; uint32_t bsw[2];
    #pragma unroll
    for (int p = 0; p < 2; p++) {
        int n = wc*32 + p*16 + (g >> 1)*8 + ri;
        boff[p] = n * 64; bsw[p] = (n >> 1) & 3;
    }
    const uint32_t qb = g & 1;

    float acc[2][4][4];
    #pragma unroll
    for (int f = 0; f < 2; f++)
        #pragma unroll
        for (int j = 0; j < 4; j++)
            #pragma unroll
            for (int e = 0; e < 4; e++) acc[f][j][e] = 0.f;

    int arow[NA], aq[NA];
    float iva[NA];
    #pragma unroll
    for (int i = 0; i < NA; i++) {
        int t = tid + i*NT; arow[i] = t >> 2; aq[i] = t & 3;
        iva[i] = RMS ? invG[row0 + arow[i]] : 1.f;
    }
    int brow[NB], bq[NB];
    #pragma unroll
    for (int j = 0; j < NB; j++) {
        int t = tid + (NA + j)*NT; brow[j] = (t >> 2) - BM; bq[j] = t & 3;
    }

    float4 sa0[NA], sa1[NA]; uint4 sbv[NB];
    const int NS = P / KS;

    auto loadg = [&](int k0) {
        #pragma unroll
        for (int i = 0; i < NA; i++) {
            const float* p = Ab + (long)(row0 + arow[i]) * P + k0 + aq[i]*8;
            sa0[i] = *(const float4*)p; sa1[i] = *(const float4*)(p + 4);
        }
        #pragma unroll
        for (int j = 0; j < NB; j++)
            sbv[j] = *(const uint4*)(BTl + (long)(col0 + brow[j]) * P + k0 + bq[j]*8);
    };
    auto stores = [&](uint32_t base) {
        #pragma unroll
        for (int i = 0; i < NA; i++) {
            uint32_t off = arow[i]*64 + (((uint32_t)aq[i] ^ ((arow[i]>>1)&3)) << 4);
            float4 a0 = sa0[i], a1 = sa1[i];
            if (RMS) { a0 = scl4(a0, iva[i]); a1 = scl4(a1, iva[i]); }
            if (TP) {
                uint4 hi, lo; cvt8_hl(a0, a1, hi, lo);
                sts128(base + off, hi); sts128(base + ALOx + off, lo);
            } else {
                sts128(base + off, cvt8_p(a0, a1));
            }
        }
        #pragma unroll
        for (int j = 0; j < NB; j++) {
            uint32_t off = brow[j]*64 + (((uint32_t)bq[j] ^ ((brow[j]>>1)&3)) << 4);
            sts128(base + BHIx + off, sbv[j]);
        }
    };

    loadg(0);
    stores(sb);
    __syncthreads();

    for (int s = 0; s < NS; s++) {
        const uint32_t cb = sb + (s & 1) * STGx;
        if (s + 1 < NS) loadg((s + 1) * KS);

        #pragma unroll
        for (int kst = 0; kst < 2; kst++) {
            uint32_t ah[2][4], bh[2][4];
            #pragma unroll
            for (int f = 0; f < 2; f++) {
                uint32_t off = aoff[f] + ((((uint32_t)(kst*2) + qa) ^ asw[f]) << 4);
                ldsm4(ah[f], cb + off);
            }
            #pragma unroll
            for (int p = 0; p < 2; p++) {
                uint32_t off = boff[p] + ((((uint32_t)(kst*2) + qb) ^ bsw[p]) << 4);
                ldsm4(bh[p], cb + BHIx + off);
            }
            #pragma unroll
            for (int f = 0; f < 2; f++)
                #pragma unroll
                for (int j = 0; j < 4; j++)
                    mma16816(acc[f][j], ah[f], bh[j>>1][(j&1)*2], bh[j>>1][(j&1)*2+1]);
            if (TP) {
                uint32_t al[2][4];
                #pragma unroll
                for (int f = 0; f < 2; f++) {
                    uint32_t off = aoff[f] + ((((uint32_t)(kst*2) + qa) ^ asw[f]) << 4);
                    ldsm4(al[f], cb + ALOx + off);
                }
                #pragma unroll
                for (int f = 0; f < 2; f++)
                    #pragma unroll
                    for (int j = 0; j < 4; j++)
                        mma16816(acc[f][j], al[f], bh[j>>1][(j&1)*2], bh[j>>1][(j&1)*2+1]);
            }
        }

        if (s + 1 < NS) stores(sb + ((s + 1) & 1) * STGx);
        __syncthreads();
    }

    // epilogue
    #pragma unroll
    for (int f = 0; f < 2; f++) {
        #pragma unroll
        for (int j = 0; j < 4; j++) {
            int r = row0 + wr*32 + f*16 + (lane >> 2);
            int c = col0 + wc*32 + j*8 + (lane & 3)*2;
            #pragma unroll
            for (int half = 0; half < 2; half++) {
                int rr = r + half*8;
                float x0 = acc[f][j][half*2], x1 = acc[f][j][half*2+1];
                if (biasl) { x0 += biasl[c]; x1 += biasl[c+1]; }
                if (res)  {
                    const float* rp = res + (long)rr*N + c;
                    x0 += rp[0]; x1 += rp[1];
                }
                if (act == 1) {
                    x0 = 0.5f*x0*(1.f + erff(x0*0.70710678118654752f));
                    x1 = 0.5f*x1*(1.f + erff(x1*0.70710678118654752f));
                }
                long ob = (long)(rr / rowseg) * segstride + (long)(rr % rowseg) * N + c;
                if (OH) {
                    __half2 hv = __floats2half2_rn(x0, x1);
                    *(__half2*)((__half*)Cb + ob) = hv;
                } else {
                    *(float2*)((float*)Cb + ob) = make_float2(x0, x1);
                }
            }
        }
    }
}

// ---------------- RMS stats: inv[row] = rsqrt(mean(x^2)+eps) ----------------
__global__ __launch_bounds__(256) void rmsstat_k(const float* __restrict__ x,
                                                 float* __restrict__ inv) {
    int row = blockIdx.x * 8 + (threadIdx.x >> 5);
    int lane = threadIdx.x & 31;
    const float* xr = x + (long)row * HH;
    float s = 0.f;
    for (int c = lane * 4; c < HH; c += 128) {
        float4 v = *(const float4*)(xr + c);
        s += v.x*v.x + v.y*v.y + v.z*v.z + v.w*v.w;
    }
    #pragma unroll
    for (int o = 16; o; o >>= 1) s += __shfl_xor_sync(~0u, s, o);
    if (lane == 0) inv[row] = rsqrtf(s / (float)HH + 1e-6f);
}

// =================== tensor-core flash attention (fp16 in) ==================
#define AT_QS 0
#define AT_KS 12288
#define AT_VS 24576
#define AT_SMEM (24576 + 64*208)

__global__ __launch_bounds__(128, 1) void attn3_k(
    const __half* __restrict__ q, const __half* __restrict__ kcat,
    const __half* __restrict__ vcat, float* __restrict__ out)
{
    extern __shared__ char smemb[];
    const uint32_t sb = smem_u32(smemb);
    const int qt = blockIdx.x, h = blockIdx.y, b = blockIdx.z;
    const int tid = threadIdx.x, lane = tid & 31, wid = tid >> 5;
    const int g = lane >> 3, ri = lane & 7;

    for (int t = tid; t < 768; t += 128) {
        int row = t / 12, c = t % 12, slab = c >> 2, cc = c & 3;
        uint4 hv = *(const uint4*)(q + (long)(b*NN + qt*64 + row)*HH + h*DH + c*8);
        uint32_t off = slab*4096 + row*64 + (((uint32_t)cc ^ ((row>>1)&3)) << 4);
        sts128(sb + AT_QS + off, hv);
    }
    __syncthreads();

    uint32_t qf[6][4];
    {
        int mrow = wid*16 + (g & 1)*8 + ri;
        uint32_t qa = g >> 1, asw = (mrow >> 1) & 3;
        #pragma unroll
        for (int k16 = 0; k16 < 6; k16++) {
            int slab = k16 >> 1, kst = k16 & 1;
            uint32_t off = slab*4096 + mrow*64
                         + ((((uint32_t)(kst*2) + qa) ^ asw) << 4);
            ldsm4(qf[k16], sb + AT_QS + off);
        }
    }

    float O[12][4];
    #pragma unroll
    for (int o = 0; o < 12; o++)
        #pragma unroll
        for (int e = 0; e < 4; e++) O[o][e] = 0.f;
    float m0 = -1e30f, m1 = -1e30f, l0 = 0.f, l1 = 0.f;

    const int nrow = (g >> 1)*8 + ri;
    const uint32_t qb = g & 1;
    const int vr = (lane & 7) + ((lane >> 3) & 1)*8;
    const int vc16 = (lane >> 4)*16;
    const int ntiles = SS/64 + qt + 1;

    for (int jt = 0; jt < ntiles; jt++) {
        __syncthreads();
        for (int t = tid; t < 768; t += 128) {
            int row = t / 12, c = t % 12;
            long jr = ((long)b*KVLEN + jt*64 + row)*HH + h*DH;
            int slab = c >> 2, cc = c & 3;
            uint4 hk = *(const uint4*)(kcat + jr + c*8);
            uint32_t koff = slab*4096 + row*64 + (((uint32_t)cc ^ ((row>>1)&3)) << 4);
            sts128(sb + AT_KS + koff, hk);
            uint4 hv = *(const uint4*)(vcat + jr + c*8);
            sts128(sb + AT_VS + row*208 + c*16, hv);
        }
        __syncthreads();

        float S[8][4];
        #pragma unroll
        for (int t8 = 0; t8 < 8; t8++)
            #pragma unroll
            for (int e = 0; e < 4; e++) S[t8][e] = 0.f;

        #pragma unroll
        for (int k16 = 0; k16 < 6; k16++) {
            int slab = k16 >> 1, kst = k16 & 1;
            #pragma unroll
            for (int p = 0; p < 4; p++) {
                int brow = p*16 + nrow;
                uint32_t off = slab*4096 + brow*64
                             + ((((uint32_t)(kst*2) + qb) ^ ((brow>>1)&3)) << 4);
                uint32_t bh[4];
                ldsm4(bh, sb + AT_KS + off);
                mma16816(S[2*p],     qf[k16], bh[0], bh[1]);
                mma16816(S[2*p + 1], qf[k16], bh[2], bh[3]);
            }
        }

        if (jt == ntiles - 1) {
            int r0 = wid*16 + (lane >> 2);
            #pragma unroll
            for (int t8 = 0; t8 < 8; t8++)
                #pragma unroll
                for (int e = 0; e < 2; e++) {
                    int col = t8*8 + 2*(lane & 3) + e;
                    if (col > r0)     S[t8][e]     = -1e30f;
                    if (col > r0 + 8) S[t8][2 + e] = -1e30f;
                }
        }

        float mx0 = -1e30f, mx1 = -1e30f;
        #pragma unroll
        for (int t8 = 0; t8 < 8; t8++) {
            mx0 = fmaxf(mx0, fmaxf(S[t8][0], S[t8][1]));
            mx1 = fmaxf(mx1, fmaxf(S[t8][2], S[t8][3]));
        }
        mx0 = fmaxf(mx0, __shfl_xor_sync(0xffffffffu, mx0, 1));
        mx0 = fmaxf(mx0, __shfl_xor_sync(0xffffffffu, mx0, 2));
        mx1 = fmaxf(mx1, __shfl_xor_sync(0xffffffffu, mx1, 1));
        mx1 = fmaxf(mx1, __shfl_xor_sync(0xffffffffu, mx1, 2));
        float mn0 = fmaxf(m0, mx0), mn1 = fmaxf(m1, mx1);
        float f0 = __expf(m0 - mn0), f1 = __expf(m1 - mn1);
        float s0 = 0.f, s1 = 0.f;
        #pragma unroll
        for (int t8 = 0; t8 < 8; t8++) {
            S[t8][0] = __expf(S[t8][0] - mn0); s0 += S[t8][0];
            S[t8][1] = __expf(S[t8][1] - mn0); s0 += S[t8][1];
            S[t8][2] = __expf(S[t8][2] - mn1); s1 += S[t8][2];
            S[t8][3] = __expf(S[t8][3] - mn1); s1 += S[t8][3];
        }
        s0 += __shfl_xor_sync(0xffffffffu, s0, 1);
        s0 += __shfl_xor_sync(0xffffffffu, s0, 2);
        s1 += __shfl_xor_sync(0xffffffffu, s1, 1);
        s1 += __shfl_xor_sync(0xffffffffu, s1, 2);
        l0 = l0*f0 + s0; l1 = l1*f1 + s1;
        m0 = mn0; m1 = mn1;
        #pragma unroll
        for (int o = 0; o < 12; o++) {
            O[o][0] *= f0; O[o][1] *= f0;
            O[o][2] *= f1; O[o][3] *= f1;
        }

        uint32_t pa[4][4];
        #pragma unroll
        for (int j16 = 0; j16 < 4; j16++) {
            pa[j16][0] = pkh2(S[2*j16][0],     S[2*j16][1]);
            pa[j16][1] = pkh2(S[2*j16][2],     S[2*j16][3]);
            pa[j16][2] = pkh2(S[2*j16 + 1][0], S[2*j16 + 1][1]);
            pa[j16][3] = pkh2(S[2*j16 + 1][2], S[2*j16 + 1][3]);
        }
        #pragma unroll
        for (int j16 = 0; j16 < 4; j16++) {
            #pragma unroll
            for (int v16 = 0; v16 < 6; v16++) {
                uint32_t bv[4];
                ldsm4t(bv, sb + AT_VS + (j16*16 + vr)*208 + v16*32 + vc16);
                mma16816(O[2*v16],     pa[j16], bv[0], bv[1]);
                mma16816(O[2*v16 + 1], pa[j16], bv[2], bv[3]);
            }
        }
    }

    float i0 = 1.f / l0, i1 = 1.f / l1;
    long rbase = (long)(b*NN + qt*64 + wid*16 + (lane >> 2))*HH + h*DH + 2*(lane & 3);
    #pragma unroll
    for (int t8 = 0; t8 < 12; t8++) {
        *(float2*)(out + rbase + t8*8) = make_float2(O[t8][0]*i0, O[t8][1]*i0);
        *(float2*)(out + rbase + 8*HH + t8*8) = make_float2(O[t8][2]*i1, O[t8][3]*i1);
    }
}

// ---------------- weight transpose+fp16 (+ optional rmsnorm weight fold) ----
__global__ void transpose_wh_k(const float* __restrict__ W, __half* __restrict__ WT,
                               int C, const float* __restrict__ nw) {
    __shared__ float tile[32][33];
    int bx = blockIdx.x, by = blockIdx.y, z = blockIdx.z;
    int tx = threadIdx.x, ty = threadIdx.y;
    const float* src = W + (long)z * HH * C;
    __half* dst = WT + (long)z * C * HH;
    #pragma unroll
    for (int j = 0; j < 32; j += 8)
        tile[ty + j][tx] = src[(long)(by * 32 + ty + j) * C + bx * 32 + tx];
    __syncthreads();
    float fac = nw ? (1.f + nw[z*HH + by*32 + tx]) : 1.f;
    #pragma unroll
    for (int j = 0; j < 32; j += 8)
        dst[(long)(bx * 32 + ty + j) * HH + by * 32 + tx] =
            __float2half_rn(tile[tx][ty + j] * fac);
}

// ---------------- fp32 -> fp16 elementwise (8 per thread, vectorized) -------
__global__ void cvt_half_k(const float4* __restrict__ E, uint4* __restrict__ O,
                           long n8) {
    long i = (long)blockIdx.x * blockDim.x + threadIdx.x;
    if (i >= n8) return;
    O[i] = cvt8_p(E[2*i], E[2*i + 1]);
}

// ---------------- embedding gather + scale ----------------------------------
__global__ void embed_k(const int* __restrict__ ids, const float* __restrict__ E,
                        float* __restrict__ hid) {
    long idx = (long)blockIdx.x * blockDim.x + threadIdx.x;
    if (idx >= (long)MROWS*HH) return;
    int col = (int)(idx % HH);
    long row = idx / HH;
    hid[idx] = E[(long)ids[row]*HH + col] * 27.712812921102035f; // sqrt(768)
}

// ---------------- RoPE cos/sin table ----------------------------------------
__global__ void rope_tab_k(float* __restrict__ ct, float* __restrict__ st) {
    int idx = blockIdx.x * blockDim.x + threadIdx.x;
    if (idx >= NN*DH) return;
    int n = idx / DH, dd = idx % DH;
    int t = (dd < DH/2) ? dd : dd - DH/2;
    float invf = __powf(10000.f, -((float)(2*t) / (float)DH));
    float fd = (float)n * invf;
    ct[idx] = cosf(fd);
    st[idx] = sinf(fd);
}

// ---------------- RoPE + q/k/v split-scatter (fp16 in/out, q pre-scaled) ----
__global__ void rope_split_k(const __half* __restrict__ qkv, __half* __restrict__ qh,
                             __half* __restrict__ kcat, __half* __restrict__ vcat,
                             const float* __restrict__ ct, const float* __restrict__ st) {
    long idx = (long)blockIdx.x * blockDim.x + threadIdx.x;
    if (idx >= (long)MROWS*HH) return;
    int col = (int)(idx % HH);
    long row = idx / HH;
    int n = (int)(row % NN);
    int b = (int)(row / NN);
    int dd = col % DH;
    const __half* base = qkv + row*(3*HH);
    float qv = __half2float(base[col]);
    float kv = __half2float(base[HH + col]);
    float vv = __half2float(base[2*HH + col]);
    float c = ct[n*DH + dd], s = st[n*DH + dd];
    float qrot = (dd < DH/2) ? -__half2float(base[col + DH/2])
                             :  __half2float(base[col - DH/2]);
    float krot = (dd < DH/2) ? -__half2float(base[HH + col + DH/2])
                             :  __half2float(base[HH + col - DH/2]);
    const float scale = 0.10206207261596575f; // 96^-0.5
    qh[row*HH + col] = __float2half_rn((qv*c + qrot*s) * scale);
    long outk = ((long)b*KVLEN + SS + n)*HH + col;
    kcat[outk] = __float2half_rn(kv*c + krot*s);
    vcat[outk] = __float2half_rn(vv);
}

// ---------------- host launchers ---------------------------------------------
template<int BM, int NT, bool TP, bool OH, bool RMS>
static void mg_t(const float* A, const float* A2, const __half* BT,
                 const float* invG, const float* bias, const float* res,
                 void* C, void* C2,
                 int M, int P, int N, int act, int rowseg, long long segstride,
                 int nz = 1, long lsA = 0, long lsC = 0, long lsB = 0,
                 long lsBias = 0) {
    constexpr int ALOx = BM * 64;
    constexpr int BHIx = TP ? 2 * ALOx : ALOx;
    constexpr int STGx = BHIx + 8192;
    dim3 grid(N / 128, M / BM, nz);
    mgemm_k<BM, NT, TP, OH, RMS><<<grid, NT, 2*STGx>>>(
        A, A2, BT, invG, bias, res, C, C2,
        M, P, N, act, rowseg, segstride, lsA, lsC, lsB, lsBias);
}

extern "C" void kernel_launch(void* const* d_in, const int* in_sizes, int n_in,
                              void* d_out, int out_size) {
    const int*   ids    = (const int*)  d_in[0];
    const float* vkey   = (const float*)d_in[1];   // [L,B,S,H]
    const float* vval   = (const float*)d_in[2];
    const float* embedW = (const float*)d_in[3];   // [V,H]
    const float* n1w    = (const float*)d_in[4];
    const float* n2w    = (const float*)d_in[5];
    const float* qkvW   = (const float*)d_in[6];   // [L,H,3H]
    const float* qkvB   = (const float*)d_in[7];
    const float* skvW   = (const float*)d_in[8];
    const float* skvB   = (const float*)d_in[9];
    const float* outW   = (const float*)d_in[10];
    const float* outB   = (const float*)d_in[11];
    const float* f1W    = (const float*)d_in[12];
    const float* f1B    = (const float*)d_in[13];
    const float* f2W    = (const float*)d_in[14];
    const float* f2B    = (const float*)d_in[15];
    float* logits = (float*)d_out;

    float *hid, *attn, *ffn, *ct, *st, *rinv;
    __half *qkvh, *qh, *kch, *vch;
    __half *qkvTh, *skvTh, *outTh, *f1Th, *f2Th, *embh;
    cudaGetSymbolAddress((void**)&hid,   g_hidden);
    cudaGetSymbolAddress((void**)&attn,  g_attn);
    cudaGetSymbolAddress((void**)&ffn,   g_ffn);
    cudaGetSymbolAddress((void**)&rinv,  g_rmsinv);
    cudaGetSymbolAddress((void**)&ct,    g_cos);
    cudaGetSymbolAddress((void**)&st,    g_sin);
    cudaGetSymbolAddress((void**)&qkvh,  g_qkvh);
    cudaGetSymbolAddress((void**)&qh,    g_qh);
    cudaGetSymbolAddress((void**)&kch,   g_kcath);
    cudaGetSymbolAddress((void**)&vch,   g_vcath);
    cudaGetSymbolAddress((void**)&qkvTh, g_qkvTh);
    cudaGetSymbolAddress((void**)&skvTh, g_skvTh);
    cudaGetSymbolAddress((void**)&outTh, g_outTh);
    cudaGetSymbolAddress((void**)&f1Th,  g_f1Th);
    cudaGetSymbolAddress((void**)&f2Th,  g_f2Th);
    cudaGetSymbolAddress((void**)&embh,  g_embedh);

    cudaFuncSetAttribute((const void*)mgemm_k<128,512,false,true,true>,
                         cudaFuncAttributeMaxDynamicSharedMemorySize, 32768);
    cudaFuncSetAttribute((const void*)mgemm_k<128,512,false,true,false>,
                         cudaFuncAttributeMaxDynamicSharedMemorySize, 32768);
    cudaFuncSetAttribute((const void*)mgemm_k<128,512,false,false,false>,
                         cudaFuncAttributeMaxDynamicSharedMemorySize, 32768);
    cudaFuncSetAttribute((const void*)mgemm_k<64,256,true,false,false>,
                         cudaFuncAttributeMaxDynamicSharedMemorySize, 32768);
    cudaFuncSetAttribute((const void*)mgemm_k<64,256,true,false,true>,
                         cudaFuncAttributeMaxDynamicSharedMemorySize, 32768);
    cudaFuncSetAttribute(attn3_k, cudaFuncAttributeMaxDynamicSharedMemorySize, AT_SMEM);

    // weight transposes into K-major fp16 (norm weights folded where consumed)
    transpose_wh_k<<<dim3(3*HH/32, HH/32, LN), dim3(32, 8)>>>(qkvW, qkvTh, 3*HH, n1w);
    transpose_wh_k<<<dim3(HH/32, HH/32, LN), dim3(32, 8)>>>(skvW, skvTh, HH, nullptr);
    transpose_wh_k<<<dim3(HH/32, HH/32, LN), dim3(32, 8)>>>(outW, outTh, HH, nullptr);
    transpose_wh_k<<<dim3(HH/32, HH/32, LN), dim3(32, 8)>>>(f1W,  f1Th,  HH, n2w);
    transpose_wh_k<<<dim3(HH/32, HH/32, LN), dim3(32, 8)>>>(f2W,  f2Th,  HH, nullptr);
    {
        long n8 = (long)VV * HH / 8;
        cvt_half_k<<<(int)((n8 + 255) / 256), 256>>>(
            (const float4*)embedW, (uint4*)embh, n8);
    }

    const int elemBlocks = (MROWS*HH + 255) / 256;
    embed_k<<<elemBlocks, 256>>>(ids, embedW, hid);
    rope_tab_k<<<(NN*DH + 255)/256, 256>>>(ct, st);

    const long HW  = (long)HH * HH;
    const long BSH = (long)BB * SS * HH;

    // ALL 24 skv GEMMs in ONE batched launch: z = 2*layer + {key,val};
    // A strided by BSH, B by HW, bias by HH, C by LBUF.
    mg_t<128,512,false,true,false>(vkey, vval, skvTh, nullptr, skvB, nullptr,
                                   kch, vch,
                                   MROWS, HH, HH, 0, SS, (long long)KVLEN*HH,
                                   2*LN, BSH, LBUF, HW, HH);

    for (int l = 0; l < LN; l++) {
        // rms stats of hidden, then qkv GEMM (norm1 folded in weights), fp16 out
        rmsstat_k<<<MROWS/8, 256>>>(hid, rinv);
        mg_t<128,512,false,true,true>(hid, nullptr, qkvTh + (long)l*3*HW, rinv,
                                      qkvB + l*3*HH, nullptr, qkvh, nullptr,
                                      MROWS, HH, 3*HH, 0, MROWS, 0);
        rope_split_k<<<elemBlocks, 256>>>(qkvh, qh, kch + l*LBUF, vch + l*LBUF,
                                          ct, st);
        attn3_k<<<dim3(NN/64, NH, BB), 128, AT_SMEM>>>(qh, kch + l*LBUF,
                                                       vch + l*LBUF, attn);
        mg_t<64,256,true,false,false>(attn, nullptr, outTh + l*HW, nullptr,
                                      outB + l*HH, hid, hid, nullptr,
                                      MROWS, HH, HH, 0, MROWS, 0);
        // rms stats again, then ffn1 (norm2 folded) + gelu
        rmsstat_k<<<MROWS/8, 256>>>(hid, rinv);
        mg_t<64,256,true,false,true>(hid, nullptr, f1Th + l*HW, rinv,
                                     f1B + l*HH, nullptr, ffn, nullptr,
                                     MROWS, HH, HH, 1, MROWS, 0);
        mg_t<64,256,true,false,false>(ffn, nullptr, f2Th + l*HW, nullptr,
                                      f2B + l*HH, hid, hid, nullptr,
                                      MROWS, HH, HH, 0, MROWS, 0);
    }

    // tied lm_head: 1-pass fp16
    mg_t<128,512,false,false,false>(hid, nullptr, embh, nullptr, nullptr,
                                    nullptr, logits, nullptr,
                                    MROWS, HH, VV, 0, MROWS, 0);
}

// round 17
// speedup vs baseline: 1.2253x; 1.0513x over previous
#include <cuda_runtime.h>
#include <cuda_bf16.h>
#include <cuda_fp16.h>
#include <math.h>
#include <stdint.h>

// Problem constants
#define LN 12
#define BB 4
#define NN 512
#define SS 512
#define VV 32000
#define HH 768
#define NH 8
#define DH 96
#define MROWS (BB*NN)          // 2048
#define KVLEN (SS+NN)          // 1024
#define LBUF ((long)BB*KVLEN*HH)   // per-layer k/v buffer elems

// ---------------- scratch (device globals; no allocation allowed) ----------
__device__ float g_hidden[MROWS*HH];
__device__ float g_attn[MROWS*HH];
__device__ float g_ffn[MROWS*HH];
__device__ float g_rmsinv[MROWS];
__device__ float g_cos[NN*DH];
__device__ float g_sin[NN*DH];
__device__ __half g_qkvh[MROWS*3*HH];
// fp16 attention operands (q pre-scaled by DH^-0.5); k/v per-layer
__device__ __half g_qh[MROWS*HH];
__device__ __half g_kcath[LN*BB*KVLEN*HH];
__device__ __half g_vcath[LN*BB*KVLEN*HH];
// K-major fp16 weights [l][N][K]
__device__ __half g_qkvTh[LN*3*HH*HH];
__device__ __half g_skvTh[LN*HH*HH];
__device__ __half g_outTh[LN*HH*HH];
__device__ __half g_f1Th[LN*HH*HH];
__device__ __half g_f2Th[LN*HH*HH];
__device__ __half g_embedh[(long)VV*HH];

// =================== helpers ================================================
__device__ __forceinline__ uint32_t smem_u32(const void* p) {
    uint32_t a;
    asm("{ .reg .u64 t; cvta.to.shared.u64 t, %1; cvt.u32.u64 %0, t; }"
        : "=r"(a) : "l"(p));
    return a;
}
__device__ __forceinline__ void sts128(uint32_t a, uint4 v) {
    asm volatile("st.shared.v4.b32 [%0], {%1,%2,%3,%4};"
        :: "r"(a), "r"(v.x), "r"(v.y), "r"(v.z), "r"(v.w) : "memory");
}
__device__ __forceinline__ void ldsm4(uint32_t (&r)[4], uint32_t addr) {
    asm volatile("ldmatrix.sync.aligned.m8n8.x4.shared.b16 {%0,%1,%2,%3}, [%4];"
        : "=r"(r[0]), "=r"(r[1]), "=r"(r[2]), "=r"(r[3]) : "r"(addr));
}
__device__ __forceinline__ void ldsm4t(uint32_t (&r)[4], uint32_t addr) {
    asm volatile("ldmatrix.sync.aligned.m8n8.x4.trans.shared.b16 {%0,%1,%2,%3}, [%4];"
        : "=r"(r[0]), "=r"(r[1]), "=r"(r[2]), "=r"(r[3]) : "r"(addr));
}
__device__ __forceinline__ void mma16816(float (&d)[4], const uint32_t (&a)[4],
                                         uint32_t b0, uint32_t b1) {
    asm volatile("mma.sync.aligned.m16n8k16.row.col.f32.f16.f16.f32 "
        "{%0,%1,%2,%3}, {%4,%5,%6,%7}, {%8,%9}, {%0,%1,%2,%3};"
        : "+f"(d[0]), "+f"(d[1]), "+f"(d[2]), "+f"(d[3])
        : "r"(a[0]), "r"(a[1]), "r"(a[2]), "r"(a[3]), "r"(b0), "r"(b1));
}
__device__ __forceinline__ uint32_t pkh2(float x, float y) {
    __half2 t = __floats2half2_rn(x, y);
    return *reinterpret_cast<uint32_t*>(&t);
}
__device__ __forceinline__ float hifh(float x) {
    return __half2float(__float2half_rn(x));
}
__device__ __forceinline__ void cvt8_hl(float4 a, float4 b, uint4& hi, uint4& lo) {
    hi.x = pkh2(a.x, a.y); hi.y = pkh2(a.z, a.w);
    hi.z = pkh2(b.x, b.y); hi.w = pkh2(b.z, b.w);
    lo.x = pkh2(a.x - hifh(a.x), a.y - hifh(a.y));
    lo.y = pkh2(a.z - hifh(a.z), a.w - hifh(a.w));
    lo.z = pkh2(b.x - hifh(b.x), b.y - hifh(b.y));
    lo.w = pkh2(b.z - hifh(b.z), b.w - hifh(b.w));
}
__device__ __forceinline__ uint4 cvt8_p(float4 a, float4 b) {
    uint4 h;
    h.x = pkh2(a.x, a.y); h.y = pkh2(a.z, a.w);
    h.z = pkh2(b.x, b.y); h.w = pkh2(b.z, b.w);
    return h;
}
__device__ __forceinline__ float4 scl4(float4 v, float s) {
    return make_float4(v.x*s, v.y*s, v.z*s, v.w*s);
}

// =================== mma.sync fp16 GEMM (templated) =========================
// C[M,N] = (invG?*A)[M,P] @ BT[N,P]^T (+bias)(+res)(gelu).
// TP: A hi/lo compensated 2-pass. OH: fp16 output. RMS: scale A row r by
// invG[r] during staging (precomputed rmsnorm; norm weight folded into BT).
// gridDim.z batching: z&1 selects A/A2,C/C2; zl=z>>1 strides A,B,C,bias.
#define KS 32

template<int BM, int NT, bool TP, bool OH, bool RMS>
__global__ void __launch_bounds__(NT, 1) mgemm_k(
    const float* __restrict__ A, const float* __restrict__ A2,
    const __half* __restrict__ BT, const float* __restrict__ invG,
    const float* __restrict__ bias, const float* res, void* Cv, void* Cv2,
    int M, int P, int N, int act, int rowseg, long long segstride,
    long lsA, long lsC, long lsB, long lsBias)
{
    constexpr int ALOx = BM * 64;
    constexpr int BHIx = TP ? 2 * ALOx : ALOx;
    constexpr int STGx = BHIx + 8192;
    constexpr int NA = (BM * 4) / NT;
    constexpr int NB = 512 / NT;

    extern __shared__ char smemb[];
    const uint32_t sb = smem_u32(smemb);
    const int tid = threadIdx.x, lane = tid & 31, wid = tid >> 5;
    const int wr = wid >> 2, wc = wid & 3;
    const int row0 = blockIdx.y * BM, col0 = blockIdx.x * 128;
    const int zl = blockIdx.z >> 1;
    const float* Ab = ((blockIdx.z & 1) ? A2 : A) + (long)zl * lsA;
    void* Cb;
    if (OH) Cb = (void*)((__half*)((blockIdx.z & 1) ? Cv2 : Cv) + (long)zl * lsC);
    else    Cb = (void*)((float*)((blockIdx.z & 1) ? Cv2 : Cv) + (long)zl * lsC);
    const __half* BTl = BT + (long)zl * lsB;
    const float* biasl = bias ? (bias + (long)zl * lsBias) : nullptr;

    const int g = lane >> 3, ri = lane & 7;
    uint32_t aoff[2]; uint32_t asw[2];
    #pragma unroll
    for (int f = 0; f < 2; f++) {
        int m = wr*32 + f*16 + (g & 1)*8 + ri;
        aoff[f] = m * 64; asw[f] = (m >> 1) & 3;
    }
    const uint32_t qa = g >> 1;
    uint32_t boff[2]; uint32_t bsw[2];
    #pragma unroll
    for (int p = 0; p < 2; p++) {
        int n = wc*32 + p*16 + (g >> 1)*8 + ri;
        boff[p] = n * 64; bsw[p] = (n >> 1) & 3;
    }
    const uint32_t qb = g & 1;

    float acc[2][4][4];
    #pragma unroll
    for (int f = 0; f < 2; f++)
        #pragma unroll
        for (int j = 0; j < 4; j++)
            #pragma unroll
            for (int e = 0; e < 4; e++) acc[f][j][e] = 0.f;

    int arow[NA], aq[NA];
    float iva[NA];
    #pragma unroll
    for (int i = 0; i < NA; i++) {
        int t = tid + i*NT; arow[i] = t >> 2; aq[i] = t & 3;
        iva[i] = RMS ? invG[row0 + arow[i]] : 1.f;
    }
    int brow[NB], bq[NB];
    #pragma unroll
    for (int j = 0; j < NB; j++) {
        int t = tid + (NA + j)*NT; brow[j] = (t >> 2) - BM; bq[j] = t & 3;
    }

    float4 sa0[NA], sa1[NA]; uint4 sbv[NB];
    const int NS = P / KS;

    auto loadg = [&](int k0) {
        #pragma unroll
        for (int i = 0; i < NA; i++) {
            const float* p = Ab + (long)(row0 + arow[i]) * P + k0 + aq[i]*8;
            sa0[i] = *(const float4*)p; sa1[i] = *(const float4*)(p + 4);
        }
        #pragma unroll
        for (int j = 0; j < NB; j++)
            sbv[j] = *(const uint4*)(BTl + (long)(col0 + brow[j]) * P + k0 + bq[j]*8);
    };
    auto stores = [&](uint32_t base) {
        #pragma unroll
        for (int i = 0; i < NA; i++) {
            uint32_t off = arow[i]*64 + (((uint32_t)aq[i] ^ ((arow[i]>>1)&3)) << 4);
            float4 a0 = sa0[i], a1 = sa1[i];
            if (RMS) { a0 = scl4(a0, iva[i]); a1 = scl4(a1, iva[i]); }
            if (TP) {
                uint4 hi, lo; cvt8_hl(a0, a1, hi, lo);
                sts128(base + off, hi); sts128(base + ALOx + off, lo);
            } else {
                sts128(base + off, cvt8_p(a0, a1));
            }
        }
        #pragma unroll
        for (int j = 0; j < NB; j++) {
            uint32_t off = brow[j]*64 + (((uint32_t)bq[j] ^ ((brow[j]>>1)&3)) << 4);
            sts128(base + BHIx + off, sbv[j]);
        }
    };

    loadg(0);
    stores(sb);
    __syncthreads();

    for (int s = 0; s < NS; s++) {
        const uint32_t cb = sb + (s & 1) * STGx;
        if (s + 1 < NS) loadg((s + 1) * KS);

        #pragma unroll
        for (int kst = 0; kst < 2; kst++) {
            uint32_t ah[2][4], bh[2][4];
            #pragma unroll
            for (int f = 0; f < 2; f++) {
                uint32_t off = aoff[f] + ((((uint32_t)(kst*2) + qa) ^ asw[f]) << 4);
                ldsm4(ah[f], cb + off);
            }
            #pragma unroll
            for (int p = 0; p < 2; p++) {
                uint32_t off = boff[p] + ((((uint32_t)(kst*2) + qb) ^ bsw[p]) << 4);
                ldsm4(bh[p], cb + BHIx + off);
            }
            #pragma unroll
            for (int f = 0; f < 2; f++)
                #pragma unroll
                for (int j = 0; j < 4; j++)
                    mma16816(acc[f][j], ah[f], bh[j>>1][(j&1)*2], bh[j>>1][(j&1)*2+1]);
            if (TP) {
                uint32_t al[2][4];
                #pragma unroll
                for (int f = 0; f < 2; f++) {
                    uint32_t off = aoff[f] + ((((uint32_t)(kst*2) + qa) ^ asw[f]) << 4);
                    ldsm4(al[f], cb + ALOx + off);
                }
                #pragma unroll
                for (int f = 0; f < 2; f++)
                    #pragma unroll
                    for (int j = 0; j < 4; j++)
                        mma16816(acc[f][j], al[f], bh[j>>1][(j&1)*2], bh[j>>1][(j&1)*2+1]);
            }
        }

        if (s + 1 < NS) stores(sb + ((s + 1) & 1) * STGx);
        __syncthreads();
    }

    // epilogue
    #pragma unroll
    for (int f = 0; f < 2; f++) {
        #pragma unroll
        for (int j = 0; j < 4; j++) {
            int r = row0 + wr*32 + f*16 + (lane >> 2);
            int c = col0 + wc*32 + j*8 + (lane & 3)*2;
            #pragma unroll
            for (int half = 0; half < 2; half++) {
                int rr = r + half*8;
                float x0 = acc[f][j][half*2], x1 = acc[f][j][half*2+1];
                if (biasl) { x0 += biasl[c]; x1 += biasl[c+1]; }
                if (res)  {
                    const float* rp = res + (long)rr*N + c;
                    x0 += rp[0]; x1 += rp[1];
                }
                if (act == 1) {
                    x0 = 0.5f*x0*(1.f + erff(x0*0.70710678118654752f));
                    x1 = 0.5f*x1*(1.f + erff(x1*0.70710678118654752f));
                }
                long ob = (long)(rr / rowseg) * segstride + (long)(rr % rowseg) * N + c;
                if (OH) {
                    __half2 hv = __floats2half2_rn(x0, x1);
                    *(__half2*)((__half*)Cb + ob) = hv;
                } else {
                    *(float2*)((float*)Cb + ob) = make_float2(x0, x1);
                }
            }
        }
    }
}

// ---------------- RMS stats: inv[row] = rsqrt(mean(x^2)+eps) ----------------
__global__ __launch_bounds__(256) void rmsstat_k(const float* __restrict__ x,
                                                 float* __restrict__ inv) {
    int row = blockIdx.x * 8 + (threadIdx.x >> 5);
    int lane = threadIdx.x & 31;
    const float* xr = x + (long)row * HH;
    float s = 0.f;
    for (int c = lane * 4; c < HH; c += 128) {
        float4 v = *(const float4*)(xr + c);
        s += v.x*v.x + v.y*v.y + v.z*v.z + v.w*v.w;
    }
    #pragma unroll
    for (int o = 16; o; o >>= 1) s += __shfl_xor_sync(~0u, s, o);
    if (lane == 0) inv[row] = rsqrtf(s / (float)HH + 1e-6f);
}

// =================== tensor-core flash attention (fp16 in) ==================
#define AT_QS 0
#define AT_KS 12288
#define AT_VS 24576
#define AT_SMEM (24576 + 64*208)

__global__ __launch_bounds__(128, 1) void attn3_k(
    const __half* __restrict__ q, const __half* __restrict__ kcat,
    const __half* __restrict__ vcat, float* __restrict__ out)
{
    extern __shared__ char smemb[];
    const uint32_t sb = smem_u32(smemb);
    const int qt = blockIdx.x, h = blockIdx.y, b = blockIdx.z;
    const int tid = threadIdx.x, lane = tid & 31, wid = tid >> 5;
    const int g = lane >> 3, ri = lane & 7;

    for (int t = tid; t < 768; t += 128) {
        int row = t / 12, c = t % 12, slab = c >> 2, cc = c & 3;
        uint4 hv = *(const uint4*)(q + (long)(b*NN + qt*64 + row)*HH + h*DH + c*8);
        uint32_t off = slab*4096 + row*64 + (((uint32_t)cc ^ ((row>>1)&3)) << 4);
        sts128(sb + AT_QS + off, hv);
    }
    __syncthreads();

    uint32_t qf[6][4];
    {
        int mrow = wid*16 + (g & 1)*8 + ri;
        uint32_t qa = g >> 1, asw = (mrow >> 1) & 3;
        #pragma unroll
        for (int k16 = 0; k16 < 6; k16++) {
            int slab = k16 >> 1, kst = k16 & 1;
            uint32_t off = slab*4096 + mrow*64
                         + ((((uint32_t)(kst*2) + qa) ^ asw) << 4);
            ldsm4(qf[k16], sb + AT_QS + off);
        }
    }

    float O[12][4];
    #pragma unroll
    for (int o = 0; o < 12; o++)
        #pragma unroll
        for (int e = 0; e < 4; e++) O[o][e] = 0.f;
    float m0 = -1e30f, m1 = -1e30f, l0 = 0.f, l1 = 0.f;

    const int nrow = (g >> 1)*8 + ri;
    const uint32_t qb = g & 1;
    const int vr = (lane & 7) + ((lane >> 3) & 1)*8;
    const int vc16 = (lane >> 4)*16;
    const int ntiles = SS/64 + qt + 1;

    for (int jt = 0; jt < ntiles; jt++) {
        __syncthreads();
        for (int t = tid; t < 768; t += 128) {
            int row = t / 12, c = t % 12;
            long jr = ((long)b*KVLEN + jt*64 + row)*HH + h*DH;
            int slab = c >> 2, cc = c & 3;
            uint4 hk = *(const uint4*)(kcat + jr + c*8);
            uint32_t koff = slab*4096 + row*64 + (((uint32_t)cc ^ ((row>>1)&3)) << 4);
            sts128(sb + AT_KS + koff, hk);
            uint4 hv = *(const uint4*)(vcat + jr + c*8);
            sts128(sb + AT_VS + row*208 + c*16, hv);
        }
        __syncthreads();

        float S[8][4];
        #pragma unroll
        for (int t8 = 0; t8 < 8; t8++)
            #pragma unroll
            for (int e = 0; e < 4; e++) S[t8][e] = 0.f;

        #pragma unroll
        for (int k16 = 0; k16 < 6; k16++) {
            int slab = k16 >> 1, kst = k16 & 1;
            #pragma unroll
            for (int p = 0; p < 4; p++) {
                int brow = p*16 + nrow;
                uint32_t off = slab*4096 + brow*64
                             + ((((uint32_t)(kst*2) + qb) ^ ((brow>>1)&3)) << 4);
                uint32_t bh[4];
                ldsm4(bh, sb + AT_KS + off);
                mma16816(S[2*p],     qf[k16], bh[0], bh[1]);
                mma16816(S[2*p + 1], qf[k16], bh[2], bh[3]);
            }
        }

        if (jt == ntiles - 1) {
            int r0 = wid*16 + (lane >> 2);
            #pragma unroll
            for (int t8 = 0; t8 < 8; t8++)
                #pragma unroll
                for (int e = 0; e < 2; e++) {
                    int col = t8*8 + 2*(lane & 3) + e;
                    if (col > r0)     S[t8][e]     = -1e30f;
                    if (col > r0 + 8) S[t8][2 + e] = -1e30f;
                }
        }

        float mx0 = -1e30f, mx1 = -1e30f;
        #pragma unroll
        for (int t8 = 0; t8 < 8; t8++) {
            mx0 = fmaxf(mx0, fmaxf(S[t8][0], S[t8][1]));
            mx1 = fmaxf(mx1, fmaxf(S[t8][2], S[t8][3]));
        }
        mx0 = fmaxf(mx0, __shfl_xor_sync(0xffffffffu, mx0, 1));
        mx0 = fmaxf(mx0, __shfl_xor_sync(0xffffffffu, mx0, 2));
        mx1 = fmaxf(mx1, __shfl_xor_sync(0xffffffffu, mx1, 1));
        mx1 = fmaxf(mx1, __shfl_xor_sync(0xffffffffu, mx1, 2));
        float mn0 = fmaxf(m0, mx0), mn1 = fmaxf(m1, mx1);
        float f0 = __expf(m0 - mn0), f1 = __expf(m1 - mn1);
        float s0 = 0.f, s1 = 0.f;
        #pragma unroll
        for (int t8 = 0; t8 < 8; t8++) {
            S[t8][0] = __expf(S[t8][0] - mn0); s0 += S[t8][0];
            S[t8][1] = __expf(S[t8][1] - mn0); s0 += S[t8][1];
            S[t8][2] = __expf(S[t8][2] - mn1); s1 += S[t8][2];
            S[t8][3] = __expf(S[t8][3] - mn1); s1 += S[t8][3];
        }
        s0 += __shfl_xor_sync(0xffffffffu, s0, 1);
        s0 += __shfl_xor_sync(0xffffffffu, s0, 2);
        s1 += __shfl_xor_sync(0xffffffffu, s1, 1);
        s1 += __shfl_xor_sync(0xffffffffu, s1, 2);
        l0 = l0*f0 + s0; l1 = l1*f1 + s1;
        m0 = mn0; m1 = mn1;
        #pragma unroll
        for (int o = 0; o < 12; o++) {
            O[o][0] *= f0; O[o][1] *= f0;
            O[o][2] *= f1; O[o][3] *= f1;
        }

        uint32_t pa[4][4];
        #pragma unroll
        for (int j16 = 0; j16 < 4; j16++) {
            pa[j16][0] = pkh2(S[2*j16][0],     S[2*j16][1]);
            pa[j16][1] = pkh2(S[2*j16][2],     S[2*j16][3]);
            pa[j16][2] = pkh2(S[2*j16 + 1][0], S[2*j16 + 1][1]);
            pa[j16][3] = pkh2(S[2*j16 + 1][2], S[2*j16 + 1][3]);
        }
        #pragma unroll
        for (int j16 = 0; j16 < 4; j16++) {
            #pragma unroll
            for (int v16 = 0; v16 < 6; v16++) {
                uint32_t bv[4];
                ldsm4t(bv, sb + AT_VS + (j16*16 + vr)*208 + v16*32 + vc16);
                mma16816(O[2*v16],     pa[j16], bv[0], bv[1]);
                mma16816(O[2*v16 + 1], pa[j16], bv[2], bv[3]);
            }
        }
    }

    float i0 = 1.f / l0, i1 = 1.f / l1;
    long rbase = (long)(b*NN + qt*64 + wid*16 + (lane >> 2))*HH + h*DH + 2*(lane & 3);
    #pragma unroll
    for (int t8 = 0; t8 < 12; t8++) {
        *(float2*)(out + rbase + t8*8) = make_float2(O[t8][0]*i0, O[t8][1]*i0);
        *(float2*)(out + rbase + 8*HH + t8*8) = make_float2(O[t8][2]*i1, O[t8][3]*i1);
    }
}

// ---------------- weight transpose+fp16 (+ optional rmsnorm weight fold) ----
__global__ void transpose_wh_k(const float* __restrict__ W, __half* __restrict__ WT,
                               int C, const float* __restrict__ nw) {
    __shared__ float tile[32][33];
    int bx = blockIdx.x, by = blockIdx.y, z = blockIdx.z;
    int tx = threadIdx.x, ty = threadIdx.y;
    const float* src = W + (long)z * HH * C;
    __half* dst = WT + (long)z * C * HH;
    #pragma unroll
    for (int j = 0; j < 32; j += 8)
        tile[ty + j][tx] = src[(long)(by * 32 + ty + j) * C + bx * 32 + tx];
    __syncthreads();
    float fac = nw ? (1.f + nw[z*HH + by*32 + tx]) : 1.f;
    #pragma unroll
    for (int j = 0; j < 32; j += 8)
        dst[(long)(bx * 32 + ty + j) * HH + by * 32 + tx] =
            __float2half_rn(tile[tx][ty + j] * fac);
}

// ---------------- fp32 -> fp16 elementwise (8 per thread, vectorized) -------
__global__ void cvt_half_k(const float4* __restrict__ E, uint4* __restrict__ O,
                           long n8) {
    long i = (long)blockIdx.x * blockDim.x + threadIdx.x;
    if (i >= n8) return;
    O[i] = cvt8_p(E[2*i], E[2*i + 1]);
}

// ---------------- embedding gather + scale ----------------------------------
__global__ void embed_k(const int* __restrict__ ids, const float* __restrict__ E,
                        float* __restrict__ hid) {
    long idx = (long)blockIdx.x * blockDim.x + threadIdx.x;
    if (idx >= (long)MROWS*HH) return;
    int col = (int)(idx % HH);
    long row = idx / HH;
    hid[idx] = E[(long)ids[row]*HH + col] * 27.712812921102035f; // sqrt(768)
}

// ---------------- RoPE cos/sin table ----------------------------------------
__global__ void rope_tab_k(float* __restrict__ ct, float* __restrict__ st) {
    int idx = blockIdx.x * blockDim.x + threadIdx.x;
    if (idx >= NN*DH) return;
    int n = idx / DH, dd = idx % DH;
    int t = (dd < DH/2) ? dd : dd - DH/2;
    float invf = __powf(10000.f, -((float)(2*t) / (float)DH));
    float fd = (float)n * invf;
    ct[idx] = cosf(fd);
    st[idx] = sinf(fd);
}

// ---------------- RoPE + q/k/v split-scatter (fp16 in/out, q pre-scaled) ----
__global__ void rope_split_k(const __half* __restrict__ qkv, __half* __restrict__ qh,
                             __half* __restrict__ kcat, __half* __restrict__ vcat,
                             const float* __restrict__ ct, const float* __restrict__ st) {
    long idx = (long)blockIdx.x * blockDim.x + threadIdx.x;
    if (idx >= (long)MROWS*HH) return;
    int col = (int)(idx % HH);
    long row = idx / HH;
    int n = (int)(row % NN);
    int b = (int)(row / NN);
    int dd = col % DH;
    const __half* base = qkv + row*(3*HH);
    float qv = __half2float(base[col]);
    float kv = __half2float(base[HH + col]);
    float vv = __half2float(base[2*HH + col]);
    float c = ct[n*DH + dd], s = st[n*DH + dd];
    float qrot = (dd < DH/2) ? -__half2float(base[col + DH/2])
                             :  __half2float(base[col - DH/2]);
    float krot = (dd < DH/2) ? -__half2float(base[HH + col + DH/2])
                             :  __half2float(base[HH + col - DH/2]);
    const float scale = 0.10206207261596575f; // 96^-0.5
    qh[row*HH + col] = __float2half_rn((qv*c + qrot*s) * scale);
    long outk = ((long)b*KVLEN + SS + n)*HH + col;
    kcat[outk] = __float2half_rn(kv*c + krot*s);
    vcat[outk] = __float2half_rn(vv);
}

// ---------------- host launchers ---------------------------------------------
template<int BM, int NT, bool TP, bool OH, bool RMS>
static void mg_t(const float* A, const float* A2, const __half* BT,
                 const float* invG, const float* bias, const float* res,
                 void* C, void* C2,
                 int M, int P, int N, int act, int rowseg, long long segstride,
                 int nz = 1, long lsA = 0, long lsC = 0, long lsB = 0,
                 long lsBias = 0) {
    constexpr int ALOx = BM * 64;
    constexpr int BHIx = TP ? 2 * ALOx : ALOx;
    constexpr int STGx = BHIx + 8192;
    dim3 grid(N / 128, M / BM, nz);
    mgemm_k<BM, NT, TP, OH, RMS><<<grid, NT, 2*STGx>>>(
        A, A2, BT, invG, bias, res, C, C2,
        M, P, N, act, rowseg, segstride, lsA, lsC, lsB, lsBias);
}

extern "C" void kernel_launch(void* const* d_in, const int* in_sizes, int n_in,
                              void* d_out, int out_size) {
    const int*   ids    = (const int*)  d_in[0];
    const float* vkey   = (const float*)d_in[1];   // [L,B,S,H]
    const float* vval   = (const float*)d_in[2];
    const float* embedW = (const float*)d_in[3];   // [V,H]
    const float* n1w    = (const float*)d_in[4];
    const float* n2w    = (const float*)d_in[5];
    const float* qkvW   = (const float*)d_in[6];   // [L,H,3H]
    const float* qkvB   = (const float*)d_in[7];
    const float* skvW   = (const float*)d_in[8];
    const float* skvB   = (const float*)d_in[9];
    const float* outW   = (const float*)d_in[10];
    const float* outB   = (const float*)d_in[11];
    const float* f1W    = (const float*)d_in[12];
    const float* f1B    = (const float*)d_in[13];
    const float* f2W    = (const float*)d_in[14];
    const float* f2B    = (const float*)d_in[15];
    float* logits = (float*)d_out;

    float *hid, *attn, *ffn, *ct, *st, *rinv;
    __half *qkvh, *qh, *kch, *vch;
    __half *qkvTh, *skvTh, *outTh, *f1Th, *f2Th, *embh;
    cudaGetSymbolAddress((void**)&hid,   g_hidden);
    cudaGetSymbolAddress((void**)&attn,  g_attn);
    cudaGetSymbolAddress((void**)&ffn,   g_ffn);
    cudaGetSymbolAddress((void**)&rinv,  g_rmsinv);
    cudaGetSymbolAddress((void**)&ct,    g_cos);
    cudaGetSymbolAddress((void**)&st,    g_sin);
    cudaGetSymbolAddress((void**)&qkvh,  g_qkvh);
    cudaGetSymbolAddress((void**)&qh,    g_qh);
    cudaGetSymbolAddress((void**)&kch,   g_kcath);
    cudaGetSymbolAddress((void**)&vch,   g_vcath);
    cudaGetSymbolAddress((void**)&qkvTh, g_qkvTh);
    cudaGetSymbolAddress((void**)&skvTh, g_skvTh);
    cudaGetSymbolAddress((void**)&outTh, g_outTh);
    cudaGetSymbolAddress((void**)&f1Th,  g_f1Th);
    cudaGetSymbolAddress((void**)&f2Th,  g_f2Th);
    cudaGetSymbolAddress((void**)&embh,  g_embedh);

    cudaFuncSetAttribute((const void*)mgemm_k<128,512,false,true,true>,
                         cudaFuncAttributeMaxDynamicSharedMemorySize, 32768);
    cudaFuncSetAttribute((const void*)mgemm_k<128,512,false,true,false>,
                         cudaFuncAttributeMaxDynamicSharedMemorySize, 32768);
    cudaFuncSetAttribute((const void*)mgemm_k<128,512,false,false,false>,
                         cudaFuncAttributeMaxDynamicSharedMemorySize, 32768);
    cudaFuncSetAttribute((const void*)mgemm_k<64,256,false,false,false>,
                         cudaFuncAttributeMaxDynamicSharedMemorySize, 24576);
    cudaFuncSetAttribute((const void*)mgemm_k<64,256,false,false,true>,
                         cudaFuncAttributeMaxDynamicSharedMemorySize, 24576);
    cudaFuncSetAttribute(attn3_k, cudaFuncAttributeMaxDynamicSharedMemorySize, AT_SMEM);

    // weight transposes into K-major fp16 (norm weights folded where consumed)
    transpose_wh_k<<<dim3(3*HH/32, HH/32, LN), dim3(32, 8)>>>(qkvW, qkvTh, 3*HH, n1w);
    transpose_wh_k<<<dim3(HH/32, HH/32, LN), dim3(32, 8)>>>(skvW, skvTh, HH, nullptr);
    transpose_wh_k<<<dim3(HH/32, HH/32, LN), dim3(32, 8)>>>(outW, outTh, HH, nullptr);
    transpose_wh_k<<<dim3(HH/32, HH/32, LN), dim3(32, 8)>>>(f1W,  f1Th,  HH, n2w);
    transpose_wh_k<<<dim3(HH/32, HH/32, LN), dim3(32, 8)>>>(f2W,  f2Th,  HH, nullptr);
    {
        long n8 = (long)VV * HH / 8;
        cvt_half_k<<<(int)((n8 + 255) / 256), 256>>>(
            (const float4*)embedW, (uint4*)embh, n8);
    }

    const int elemBlocks = (MROWS*HH + 255) / 256;
    embed_k<<<elemBlocks, 256>>>(ids, embedW, hid);
    rope_tab_k<<<(NN*DH + 255)/256, 256>>>(ct, st);

    const long HW  = (long)HH * HH;
    const long BSH = (long)BB * SS * HH;

    // ALL 24 skv GEMMs in ONE batched launch: z = 2*layer + {key,val}
    mg_t<128,512,false,true,false>(vkey, vval, skvTh, nullptr, skvB, nullptr,
                                   kch, vch,
                                   MROWS, HH, HH, 0, SS, (long long)KVLEN*HH,
                                   2*LN, BSH, LBUF, HW, HH);

    for (int l = 0; l < LN; l++) {
        rmsstat_k<<<MROWS/8, 256>>>(hid, rinv);
        mg_t<128,512,false,true,true>(hid, nullptr, qkvTh + (long)l*3*HW, rinv,
                                      qkvB + l*3*HH, nullptr, qkvh, nullptr,
                                      MROWS, HH, 3*HH, 0, MROWS, 0);
        rope_split_k<<<elemBlocks, 256>>>(qkvh, qh, kch + l*LBUF, vch + l*LBUF,
                                          ct, st);
        attn3_k<<<dim3(NN/64, NH, BB), 128, AT_SMEM>>>(qh, kch + l*LBUF,
                                                       vch + l*LBUF, attn);
        // residual-stream GEMMs now 1-pass fp16 (error budget analysis R15)
        mg_t<64,256,false,false,false>(attn, nullptr, outTh + l*HW, nullptr,
                                       outB + l*HH, hid, hid, nullptr,
                                       MROWS, HH, HH, 0, MROWS, 0);
        rmsstat_k<<<MROWS/8, 256>>>(hid, rinv);
        mg_t<64,256,false,false,true>(hid, nullptr, f1Th + l*HW, rinv,
                                      f1B + l*HH, nullptr, ffn, nullptr,
                                      MROWS, HH, HH, 1, MROWS, 0);
        mg_t<64,256,false,false,false>(ffn, nullptr, f2Th + l*HW, nullptr,
                                       f2B + l*HH, hid, hid, nullptr,
                                       MROWS, HH, HH, 0, MROWS, 0);
    }

    // tied lm_head: 1-pass fp16
    mg_t<128,512,false,false,false>(hid, nullptr, embh, nullptr, nullptr,
                                    nullptr, logits, nullptr,
                                    MROWS, HH, VV, 0, MROWS, 0);
}